// round 11
// baseline (speedup 1.0000x reference)
#include <cuda_runtime.h>
#include <cstdint>
#include <cstddef>

// Problem constants
#define BATCH 16384
#define F 512
#define CLUSTER 16       // one 16-CTA cluster (non-portable size), 1 GPC
#define TPB 512          // 16 warps; warp w owns columns b*32+2w, +1
#define SLOTS 4          // (epoch,value) slot ring; 2 suffice by dataflow

// Scratch (device globals: no allocation allowed in kernel_launch)
__device__ __align__(16) float g_xwz[(size_t)BATCH * F];   // x@Wz + bz
__device__ __align__(16) float g_xwh[(size_t)BATCH * F];   // x@Wh + bh

// ---------------------------------------------------------------------------
// PTX helpers
// ---------------------------------------------------------------------------
__device__ __forceinline__ uint32_t smem_u32(const void* p) {
    uint32_t a;
    asm("{ .reg .u64 t; cvta.to.shared.u64 t, %1; cvt.u32.u64 %0, t; }"
        : "=r"(a) : "l"(p));
    return a;
}
__device__ __forceinline__ unsigned long long fma2(
    unsigned long long a, unsigned long long b, unsigned long long c) {
    unsigned long long d;
    asm("fma.rn.f32x2 %0, %1, %2, %3;" : "=l"(d) : "l"(a), "l"(b), "l"(c));
    return d;
}
__device__ __forceinline__ unsigned long long add2(
    unsigned long long a, unsigned long long b) {
    unsigned long long d;
    asm("add.rn.f32x2 %0, %1, %2;" : "=l"(d) : "l"(a), "l"(b));
    return d;
}
__device__ __forceinline__ float pair_sum(unsigned long long p) {
    uint32_t lo, hi;
    asm("mov.b64 {%0, %1}, %2;" : "=r"(lo), "=r"(hi) : "l"(p));
    return __uint_as_float(lo) + __uint_as_float(hi);
}
__device__ __forceinline__ unsigned long long pack2f(float a0, float a1) {
    unsigned long long p;
    asm("mov.b64 %0, {%1, %2};" : "=l"(p)
        : "r"(__float_as_uint(a0)), "r"(__float_as_uint(a1)));
    return p;
}
__device__ __forceinline__ unsigned long long pack2u(uint32_t a0, uint32_t a1) {
    unsigned long long p;
    asm("mov.b64 %0, {%1, %2};" : "=l"(p) : "r"(a0), "r"(a1));
    return p;
}
__device__ __forceinline__ void unpack2(unsigned long long p,
                                        uint32_t& lo, uint32_t& hi) {
    asm("mov.b64 {%0, %1}, %2;" : "=r"(lo), "=r"(hi) : "l"(p));
}
__device__ __forceinline__ uint32_t mapa_rank(uint32_t laddr, int rank) {
    uint32_t r;
    asm("mapa.shared::cluster.u32 %0, %1, %2;" : "=r"(r) : "r"(laddr), "r"(rank));
    return r;
}
__device__ __forceinline__ void dsmem_store_u64(uint32_t raddr,
                                                unsigned long long v) {
    asm volatile("st.shared::cluster.u64 [%0], %1;"
                 :: "r"(raddr), "l"(v) : "memory");
}
__device__ __forceinline__ void lds_v2_u64(uint32_t addr,
                                           unsigned long long& a,
                                           unsigned long long& b) {
    asm volatile("ld.shared.v2.u64 {%0, %1}, [%2];"
                 : "=l"(a), "=l"(b) : "r"(addr));
}
__device__ __forceinline__ void cluster_arrive() {
    asm volatile("barrier.cluster.arrive.aligned;" ::: "memory");
}
__device__ __forceinline__ void cluster_wait() {
    asm volatile("barrier.cluster.wait.aligned;" ::: "memory");
}

// ---------------------------------------------------------------------------
// Phase 1: batched GEMM  C = A(16384x512) * W(512x512) + bias
// ---------------------------------------------------------------------------
#define BM 64
#define BN 64
#define BKK 16

__global__ void __launch_bounds__(256) gemm_kernel(
    const float* __restrict__ A,
    const float* __restrict__ Wz, const float* __restrict__ bz,
    const float* __restrict__ Wh, const float* __restrict__ bh)
{
    const float* B    = (blockIdx.z == 0) ? Wz : Wh;
    const float* bias = (blockIdx.z == 0) ? bz : bh;
    float*       C    = (blockIdx.z == 0) ? g_xwz : g_xwh;

    __shared__ float As[BKK][BM];
    __shared__ float Bs[BKK][BN];

    const int row0 = blockIdx.y * BM;
    const int col0 = blockIdx.x * BN;
    const int tid  = threadIdx.x;

    const int a_m = tid >> 2;
    const int a_k = (tid & 3) * 4;
    const int b_k = tid >> 4;
    const int b_n = (tid & 15) * 4;

    const int ty = tid >> 4;
    const int tx = tid & 15;

    float acc[4][4] = {};

    for (int k0 = 0; k0 < F; k0 += BKK) {
        float4 av = *(const float4*)(A + (size_t)(row0 + a_m) * F + k0 + a_k);
        As[a_k + 0][a_m] = av.x;
        As[a_k + 1][a_m] = av.y;
        As[a_k + 2][a_m] = av.z;
        As[a_k + 3][a_m] = av.w;
        float4 bv = *(const float4*)(B + (size_t)(k0 + b_k) * F + col0 + b_n);
        *(float4*)&Bs[b_k][b_n] = bv;
        __syncthreads();
#pragma unroll
        for (int k = 0; k < BKK; k++) {
            float ar[4], br[4];
            *(float4*)ar = *(const float4*)&As[k][ty * 4];
            *(float4*)br = *(const float4*)&Bs[k][tx * 4];
#pragma unroll
            for (int i = 0; i < 4; i++)
#pragma unroll
                for (int jj = 0; jj < 4; jj++)
                    acc[i][jj] = fmaf(ar[i], br[jj], acc[i][jj]);
        }
        __syncthreads();
    }

    float4 bv;
    bv.x = __ldg(&bias[col0 + tx * 4 + 0]);
    bv.y = __ldg(&bias[col0 + tx * 4 + 1]);
    bv.z = __ldg(&bias[col0 + tx * 4 + 2]);
    bv.w = __ldg(&bias[col0 + tx * 4 + 3]);
#pragma unroll
    for (int i = 0; i < 4; i++) {
        float4 o;
        o.x = acc[i][0] + bv.x;
        o.y = acc[i][1] + bv.y;
        o.z = acc[i][2] + bv.z;
        o.w = acc[i][3] + bv.w;
        *(float4*)(C + (size_t)(row0 + ty * 4 + i) * F + col0 + tx * 4) = o;
    }
}

// ---------------------------------------------------------------------------
// Phase 2: scan, one 16-CTA cluster, self-synchronizing (epoch,value) words
// with THROTTLED polling (the R10 livelock fix).
//
// Layout: CTA b owns columns b*32..+31; warp w owns cols 2w,2w+1; lane l
// handles column j0+(l>>4), state rows (l&15)*32..+31, register U (f32x2).
//
// Handoff: at step t every lane publishes ONE aligned 8-byte word
//     (epoch = t+1) << 32  |  bits(m_t[mycol])
// to rank hl's sval[t&3] slot via st.shared::cluster.u64 (aligned 8B store:
// data IS the readiness signal; one DSMEM hop). Consumers poll LOCAL smem;
// between failed rounds they run a ~16-deep dependent FMA chain (throttles
// poll bandwidth so incoming remote stores are not starved — R10 livelocked
// on exactly this), escalating to __nanosleep after 32 rounds.
//
// Slot-ring safety (SLOTS=4; 2 suffice): a warp writes step t only after
// observing every producer's step t-1 words; each of those was published
// after its producer finished reading step t-2. Hence all readers of the
// overwritten slot are done. Gang-scheduled cluster, local-only polling.
// ---------------------------------------------------------------------------
__global__ void __launch_bounds__(TPB, 1) scan_kernel(
    const float* __restrict__ Uz,
    const float* __restrict__ Uh,
    float* __restrict__ out)
{
    __shared__ __align__(16) unsigned long long sval[SLOTS][F];  // 16 KB

    const int b = blockIdx.x;              // cluster rank
    const int w = threadIdx.x >> 5;
    const int l = threadIdx.x & 31;
    const int hw = l >> 4;
    const int hl = l & 15;                 // producer rank for this lane's rows
    const int mycol = b * 32 + w * 2 + hw;
    const int rbase = hl * 32;
    const bool head = (hl == 0);           // one writer of out[] per column

    // Zero all epochs (stale smem would alias old epochs across graph replays)
    for (int i = threadIdx.x; i < SLOTS * F; i += TPB)
        ((unsigned long long*)sval)[i] = 0ull;
    __syncthreads();
    cluster_arrive();                      // all CTAs' slots zeroed before use

    // Preload packed U slices (rows rbase+2i, rbase+2i+1 of column mycol)
    unsigned long long uzp[16], uhp[16];
#pragma unroll
    for (int i = 0; i < 16; i++) {
        uzp[i] = pack2f(Uz[(size_t)(rbase + 2 * i) * F + mycol],
                        Uz[(size_t)(rbase + 2 * i + 1) * F + mycol]);
        uhp[i] = pack2f(Uh[(size_t)(rbase + 2 * i) * F + mycol],
                        Uh[(size_t)(rbase + 2 * i + 1) * F + mycol]);
    }

    // Producer slot address for column mycol (bank-swizzled):
    // chunk jj of region rg lives at physical chunk rg*16+((jj&8)|((jj&7)^(rg&7)))
    const int Lc   = mycol >> 1;
    const int rg   = mycol >> 5;
    const int jj   = Lc & 15;
    const int phys = rg * 16 + ((jj & 8) | ((jj & 7) ^ (rg & 7)));
    const int s64  = phys * 2 + (mycol & 1);
    uint32_t dstv[SLOTS];
#pragma unroll
    for (int s = 0; s < SLOTS; s++)
        dstv[s] = mapa_rank(smem_u32(&sval[s][0]) + s64 * 8, hl);

    cluster_wait();

    float xz_p = __ldg(&g_xwz[mycol]);     // x@W terms for t = 0
    float xh_p = __ldg(&g_xwh[mycol]);
    float mj = 0.f;                        // m_{t-1}[mycol], register-carried
    float fill = (float)(threadIdx.x + 1) * 1.0e-18f;   // backoff chain carrier

    for (int t = 0; t < BATCH; t++) {
        unsigned long long az0 = 0ull, az1 = 0ull, ah0 = 0ull, ah1 = 0ull;

        if (t > 0) {
            const uint32_t slotbase =
                smem_u32(&sval[(t - 1) & (SLOTS - 1)][0]);
            const uint32_t tep = (uint32_t)t;          // expected epoch
            unsigned long long mvp[16];
            int rounds = 0;
            for (;;) {
                unsigned bad = 0u;
#pragma unroll
                for (int j = 0; j < 16; j++) {
                    const int pj = (j & 8) | ((j & 7) ^ (hl & 7));
                    const uint32_t addr = slotbase + ((hl * 16 + pj) << 4);
                    unsigned long long v0, v1;
                    lds_v2_u64(addr, v0, v1);
                    uint32_t lo0, hi0, lo1, hi1;
                    unpack2(v0, lo0, hi0);
                    unpack2(v1, lo1, hi1);
                    bad |= (hi0 ^ tep) | (hi1 ^ tep);
                    mvp[j] = pack2u(lo0, lo1);         // rows rbase+2j, +2j+1
                }
                if (!__any_sync(0xffffffffu, bad != 0u)) break;
                // THROTTLE: ~16-deep dependent FMA chain (~64 cyc) between
                // rounds keeps the smem crossbar free for incoming stores.
#pragma unroll
                for (int i = 0; i < 16; i++)
                    fill = fmaf(fill, 1.0000001f, 1.0e-30f);
                if (++rounds > 32) { __nanosleep(200); rounds = 16; }
            }

#pragma unroll
            for (int j = 0; j < 16; j += 2) {
                az0 = fma2(mvp[j],     uzp[j],     az0);
                az1 = fma2(mvp[j + 1], uzp[j + 1], az1);
                ah0 = fma2(mvp[j],     uhp[j],     ah0);
                ah1 = fma2(mvp[j + 1], uhp[j + 1], ah1);
            }
        }

        float az = pair_sum(add2(az0, az1));
        float ah = pair_sum(add2(ah0, ah1));
        // 4-level butterfly inside the half-warp: sum lands in every lane
#pragma unroll
        for (int s = 8; s > 0; s >>= 1) {
            az += __shfl_xor_sync(0xffffffffu, az, s);
            ah += __shfl_xor_sync(0xffffffffu, ah, s);
        }

        // All lanes compute the gate (register-carried mj; no broadcast shfl)
        const float zp = az + xz_p;
        const float hp = ah + xh_p;
        const float z = __fdividef(1.f, 1.f + __expf(-zp));            // sigmoid
        const float h = 1.f - __fdividef(2.f, __expf(2.f * hp) + 1.f); // tanh
        const float mn = fmaf(z, h - mj, mj);

        if (head) out[(size_t)t * F + mycol] = mn;
        mj = mn;

        if (t + 1 < BATCH) {
            const unsigned long long pk =
                ((unsigned long long)(uint32_t)(t + 1) << 32) |
                (unsigned long long)__float_as_uint(mn);
            dsmem_store_u64(dstv[t & (SLOTS - 1)], pk);
            // Prefetch x@W for t+1 (off the critical path)
            xz_p = __ldg(&g_xwz[(size_t)(t + 1) * F + mycol]);
            xh_p = __ldg(&g_xwh[(size_t)(t + 1) * F + mycol]);
        }
    }

    // Keep the backoff chain live; condition can never hold.
    if (__float_as_uint(fill) == 0xdeadbeefu) out[0] = fill;

    // No CTA may exit while peers' DSMEM stores targeting it are in flight.
    cluster_arrive();
    cluster_wait();
}

// ---------------------------------------------------------------------------
// Launch: GEMMs -> single-cluster scan. All graph-capturable.
// ---------------------------------------------------------------------------
extern "C" void kernel_launch(void* const* d_in, const int* in_sizes, int n_in,
                              void* d_out, int out_size)
{
    const float* x  = (const float*)d_in[0];
    const float* Wz = (const float*)d_in[1];
    const float* Uz = (const float*)d_in[2];
    const float* bz = (const float*)d_in[3];
    const float* Wh = (const float*)d_in[4];
    const float* Uh = (const float*)d_in[5];
    const float* bh = (const float*)d_in[6];
    float* out = (float*)d_out;

    dim3 ggrid(F / BN, BATCH / BM, 2);   // 8 x 256 x 2
    gemm_kernel<<<ggrid, 256>>>(x, Wz, bz, Wh, bh);

    cudaFuncSetAttribute(scan_kernel,
                         cudaFuncAttributeNonPortableClusterSizeAllowed, 1);
    cudaLaunchConfig_t cfg = {};
    cfg.gridDim  = dim3(CLUSTER, 1, 1);
    cfg.blockDim = dim3(TPB, 1, 1);
    cfg.dynamicSmemBytes = 0;
    cfg.stream = 0;
    cudaLaunchAttribute attrs[1];
    attrs[0].id = cudaLaunchAttributeClusterDimension;
    attrs[0].val.clusterDim.x = CLUSTER;
    attrs[0].val.clusterDim.y = 1;
    attrs[0].val.clusterDim.z = 1;
    cfg.attrs = attrs;
    cfg.numAttrs = 1;
    cudaLaunchKernelEx(&cfg, scan_kernel, Uz, Uh, out);
}